// round 13
// baseline (speedup 1.0000x reference)
#include <cuda_runtime.h>
#include <cuda_fp16.h>
#include <cstdint>
#include <math.h>

#define NB 8
#define SLEN 2048
#define DMODEL 1024
#define KDIM 1152
#define LMAX 4608
#define NVMAX 4608
#define MTOT (NB * 2304)   // 18432

// ---------------- device-global scratch (no allocs allowed) ----------------
__device__ int g_src[NB][LMAX];    // >=0: gather text pos; -2: visual (GEMM writes); -1: pad
__device__ int g_X[NB][LMAX];      // mask row r: ones for c < X_r, zeros after
__device__ int g_vdst[NB][NVMAX];  // visual token j -> fused row (or -1)
__device__ __half g_Ah[(size_t)MTOT * KDIM];     // visual features as fp16 (42.5MB)
__device__ __half g_Wh[(size_t)DMODEL * KDIM];   // W transposed to [N, K] fp16 (2.4MB)

// ---------------- PTX helpers ----------------
__device__ __forceinline__ uint32_t smem_u32(const void* p) {
    uint32_t a;
    asm("{ .reg .u64 t; cvta.to.shared.u64 t, %1; cvt.u32.u64 %0, t; }" : "=r"(a) : "l"(p));
    return a;
}
__device__ __forceinline__ void cp16(void* smem, const void* gmem) {
    uint32_t s = smem_u32(smem);
    asm volatile("cp.async.cg.shared.global [%0], [%1], 16;\n" :: "r"(s), "l"(gmem));
}
#define CP_COMMIT() asm volatile("cp.async.commit_group;\n")
#define CP_WAIT(n)  asm volatile("cp.async.wait_group %0;\n" :: "n"(n))

// TMA bulk store: smem -> global, size multiple of 16, both 16B aligned.
// bulk-async-group counters are SEPARATE from cp.async.cg commit/wait groups.
__device__ __forceinline__ void bulk_s2g(void* gptr, const void* sptr, uint32_t bytes) {
    asm volatile("cp.async.bulk.global.shared::cta.bulk_group [%0], [%1], %2;"
                 :: "l"(gptr), "r"(smem_u32(sptr)), "r"(bytes) : "memory");
}
#define BULK_COMMIT() asm volatile("cp.async.bulk.commit_group;" ::: "memory")
#define BULK_WAIT0()  asm volatile("cp.async.bulk.wait_group 0;" ::: "memory")

#define LDSM_X4(r, addr) \
    asm volatile("ldmatrix.sync.aligned.m8n8.x4.shared.b16 {%0,%1,%2,%3}, [%4];" \
        : "=r"((r)[0]), "=r"((r)[1]), "=r"((r)[2]), "=r"((r)[3]) : "r"(addr))

__device__ __forceinline__ void mma_f16(float* d, const uint32_t* a, const uint32_t* b) {
    asm volatile(
        "mma.sync.aligned.m16n8k16.row.col.f32.f16.f16.f32 "
        "{%0,%1,%2,%3}, {%4,%5,%6,%7}, {%8,%9}, {%0,%1,%2,%3};\n"
        : "+f"(d[0]), "+f"(d[1]), "+f"(d[2]), "+f"(d[3])
        : "r"(a[0]), "r"(a[1]), "r"(a[2]), "r"(a[3]), "r"(b[0]), "r"(b[1]));
}

// ============ prologue: plan + conv_a + prep_w in ONE launch ================
__global__ void __launch_bounds__(256) prologue_kernel(
    const float* __restrict__ A,       // visual
    const float* __restrict__ W,
    const int*   __restrict__ texts,
    const int*   __restrict__ img_id_p,
    int nvis, int L, int n8, int nConv, int nPrep)
{
    const int bid = blockIdx.x;
    const int tid = threadIdx.x;

    // ---- type A: conv (fp32 -> fp16 of visual) ----
    if (bid < nConv) {
        int i = bid * 256 + tid;
        if (i >= n8) return;
        const float4* src = reinterpret_cast<const float4*>(A) + (size_t)i * 2;
        float4 v0 = src[0], v1 = src[1];
        float4 o;
        o.x = __uint_as_float((uint32_t)__half_as_ushort(__float2half_rn(v0.x)) |
                              ((uint32_t)__half_as_ushort(__float2half_rn(v0.y)) << 16));
        o.y = __uint_as_float((uint32_t)__half_as_ushort(__float2half_rn(v0.z)) |
                              ((uint32_t)__half_as_ushort(__float2half_rn(v0.w)) << 16));
        o.z = __uint_as_float((uint32_t)__half_as_ushort(__float2half_rn(v1.x)) |
                              ((uint32_t)__half_as_ushort(__float2half_rn(v1.y)) << 16));
        o.w = __uint_as_float((uint32_t)__half_as_ushort(__float2half_rn(v1.z)) |
                              ((uint32_t)__half_as_ushort(__float2half_rn(v1.w)) << 16));
        __stcs(reinterpret_cast<float4*>(g_Ah) + i, o);
        return;
    }

    __shared__ float t[32][33];       // prep
    __shared__ int s_pos[64];         // plan
    __shared__ int s_n;

    // ---- type B: prep_w (transpose W -> [N,K] fp16) ----
    if (bid < nConv + nPrep) {
        int sub = bid - nConv;
        int k0 = (sub % (KDIM / 32)) * 32;
        int n0 = (sub / (KDIM / 32)) * 32;
        int tx = tid & 31, ty = tid >> 5;
        #pragma unroll
        for (int i = ty; i < 32; i += 8)
            t[i][tx] = W[(size_t)(k0 + i) * DMODEL + n0 + tx];
        __syncthreads();
        #pragma unroll
        for (int i = ty; i < 32; i += 8)
            g_Wh[(size_t)(n0 + i) * KDIM + k0 + tx] = __float2half_rn(t[tx][i]);
        return;
    }

    // ---- type C: plan ----
    int b = bid - nConv - nPrep;
    int img_id = *img_id_p;
    const int* tx_ = texts + b * SLEN;
    if (tid == 0) s_n = 0;
    __syncthreads();
    for (int p = tid; p < SLEN; p += blockDim.x)
        if (tx_[p] == img_id) { int k = atomicAdd(&s_n, 1); if (k < 64) s_pos[k] = p; }
    __syncthreads();
    int n = min(s_n, 64);
    if (tid == 0) {
        for (int i = 1; i < n; i++) {
            int v = s_pos[i]; int j = i - 1;
            while (j >= 0 && s_pos[j] > v) { s_pos[j + 1] = s_pos[j]; j--; }
            s_pos[j + 1] = v;
        }
    }
    __syncthreads();
    int per = (n > 0) ? (nvis / n) : 0;
    int len = (n > 0) ? (SLEN - n + n * per) : SLEN;
    for (int p = tid; p < SLEN; p += blockDim.x) {
        if (tx_[p] == img_id) continue;
        int k = 0;
        while (k < n && s_pos[k] < p) k++;
        int fp = (p - k) + k * per;
        g_src[b][fp] = p;
        g_X[b][fp]   = fp + 1;
    }
    for (int j = tid; j < nvis; j += blockDim.x) {
        int dst = -1;
        if (n > 0 && j < n * per) {
            int i = j / per;
            dst = (s_pos[i] - i) + i * per + (j - i * per);
            g_src[b][dst] = -2;
            g_X[b][dst]   = (s_pos[i] - i) + (i + 1) * per;
        }
        g_vdst[b][j] = dst;
    }
    for (int l = len + tid; l < L; l += blockDim.x) { g_src[b][l] = -1; g_X[b][l] = 0; }
}

// ==== fused kernel: gemm blocks (mask via background TMA) + gather blocks ==
#define GBM 128
#define GBN 128
#define GBK 32
#define STR_B 80                     // bytes per smem row (40 halves, ldmatrix conflict-free)
#define ATILE_B (128 * STR_B)        // 10240
#define STAGE_B (2 * ATILE_B)        // 20480
#define NSTG 4
#define MCHUNK 4096                  // bulk-store chunk (bytes)
// layout: stages [0,81920) | bias 512B | sX 128B | pad | ones 4KB | zeros 4KB
#define OFF_BIAS  (NSTG * STAGE_B)          // 81920
#define OFF_SX    (OFF_BIAS + 512)          // 82432
#define OFF_ONES  (OFF_SX + 640)            // 83072 (16B aligned)
#define OFF_ZEROS (OFF_ONES + MCHUNK)       // 87168
#define GEMM_SMEM (OFF_ZEROS + MCHUNK)      // 91264; 2 CTAs/SM

__global__ void __launch_bounds__(256, 2) fused_kernel(
    const float* __restrict__ bias,
    const float* __restrict__ emb,
    const int*   __restrict__ texts,
    float* __restrict__ out_fused,
    float* __restrict__ out_mask,
    int nvis, int L, int nGemm, int nMask, int nGath, int mRowBlks)
{
    extern __shared__ char smem[];
    const int bid = blockIdx.x;
    const int tid = threadIdx.x;
    const int wid = tid >> 5, lane = tid & 31;

    // interleave: first 2*min blocks alternate gemm(even)/gather(odd); tail = gemm
    const int half2 = 2 * min(nGath, nGemm);
    int sub;
    bool isGather;
    if (bid < half2) { isGather = (bid & 1); sub = bid >> 1; }
    else { isGather = false; sub = (half2 >> 1) + (bid - half2); }

    // ------------------------ gather blocks ------------------------
    if (isGather) {
        if (sub >= nGath) return;
        #pragma unroll
        for (int i = 0; i < 4; i++) {
            int row = sub * 32 + wid * 4 + i;
            if (row >= NB * L) break;
            int b = row / L, l = row - b * L;
            int src = g_src[b][l];
            if (src == -2) continue;  // visual row: GEMM epilogue writes it
            float4* dst = reinterpret_cast<float4*>(out_fused + ((size_t)b * L + l) * DMODEL);
            if (src < 0) {
                float4 z = make_float4(0.f, 0.f, 0.f, 0.f);
                #pragma unroll
                for (int k = 0; k < 8; k++) __stcs(dst + lane + k * 32, z);
                continue;
            }
            int tok = texts[b * SLEN + src];
            const float4* s = reinterpret_cast<const float4*>(emb + (size_t)tok * DMODEL);
            float4 v[8];
            #pragma unroll
            for (int k = 0; k < 8; k++) v[k] = s[lane + k * 32];
            #pragma unroll
            for (int k = 0; k < 8; k++) __stcs(dst + lane + k * 32, v[k]);
        }
        return;
    }

    // ----------- gemm blocks; mask chunk rides the TMA engine --------------
    if (sub >= nGemm) return;
    float* sBias = reinterpret_cast<float*>(smem + OFF_BIAS);
    int*   sXm   = reinterpret_cast<int*>(smem + OFF_SX);
    float* ones  = reinterpret_cast<float*>(smem + OFF_ONES);
    float* zeros = reinterpret_cast<float*>(smem + OFF_ZEROS);

    const int nb0 = (sub & 7) * GBN;        // 8 N-blocks (DMODEL/128)
    const int gm0 = (sub >> 3) * GBM;
    const int wm = wid & 1;       // 2 warps along M (64 rows)
    const int wn = wid >> 1;      // 4 warps along N (32 cols)
    const int grp = lane >> 2;
    const int qid = lane & 3;

    if (tid < 128) sBias[tid] = bias[nb0 + tid];

    // mask setup: this block also owns mask chunk `sub` (if any)
    const bool hasMask = (sub < nMask);
    int mb = 0, mr0 = 0, mrmax = 0;
    if (hasMask) {
        mb    = sub / mRowBlks;
        mr0   = (sub - mb * mRowBlks) * 32;
        mrmax = min(32, L - mr0);
        // fill pattern buffers (1024 floats each) + per-row prefix lengths
        for (int i = tid; i < MCHUNK / 4; i += 256) { ones[i] = 1.f; zeros[i] = 0.f; }
        if (tid < 32) sXm[tid] = (mr0 + tid < L) ? g_X[mb][mr0 + tid] : 0;
    }

    const __half* Ag = g_Ah + (size_t)gm0 * KDIM;
    const __half* Bg = g_Wh + (size_t)nb0 * KDIM;

    float acc[4][4][4];
    #pragma unroll
    for (int i = 0; i < 4; i++)
        #pragma unroll
        for (int j = 0; j < 4; j++)
            #pragma unroll
            for (int k = 0; k < 4; k++) acc[i][j][k] = 0.f;

    const int KT = KDIM / GBK;  // 36

    auto issue = [&](int kt) {
        int s = kt % NSTG;
        char* dA = smem + s * STAGE_B;
        char* dB = dA + ATILE_B;
        #pragma unroll
        for (int v = tid; v < 512; v += 256) {
            int row = v >> 2, c = v & 3;
            cp16(dA + row * STR_B + c * 16, Ag + (size_t)row * KDIM + kt * GBK + c * 8);
        }
        #pragma unroll
        for (int v = tid; v < 512; v += 256) {
            int row = v >> 2, c = v & 3;
            cp16(dB + row * STR_B + c * 16, Bg + (size_t)row * KDIM + kt * GBK + c * 8);
        }
        CP_COMMIT();
    };

    issue(0);
    issue(1);
    issue(2);

    // ---- launch the mask chunk on the TMA engine (background writes) ----
    if (hasMask) {
        __syncthreads();  // pattern buffers + sXm complete
        asm volatile("fence.proxy.async.shared::cta;" ::: "memory");
        if (tid < mrmax) {
            int X = sXm[tid];
            if (X < 0) X = 0;
            if (X > L) X = L;
            float* grow = out_mask + ((size_t)mb * L + mr0 + tid) * (size_t)L;
            int bytes1 = X * 4;
            int n1  = bytes1 & ~15;            // ones bulk prefix (16B mult)
            int c16 = (bytes1 + 15) & ~15;     // zeros bulk start
            for (int off = 0; off < n1; off += MCHUNK) {
                int len = n1 - off; if (len > MCHUNK) len = MCHUNK;
                bulk_s2g((char*)grow + off, ones, (uint32_t)len);
            }
            if (c16 > n1) {                    // boundary 16B via scalar STG
                #pragma unroll
                for (int f = 0; f < 4; f++) {
                    int idx = (n1 >> 2) + f;
                    grow[idx] = (idx < X) ? 1.f : 0.f;
                }
            }
            int zb = L * 4 - c16;
            for (int off = 0; off < zb; off += MCHUNK) {
                int len = zb - off; if (len > MCHUNK) len = MCHUNK;
                bulk_s2g((char*)grow + c16 + off, zeros, (uint32_t)len);
            }
        }
        BULK_COMMIT();
    }

    const int a_row = wm * 64 + (lane & 15);
    const int a_colb = (lane >> 4) * 16;
    const int b_row0 = wn * 32 + (lane & 7) + ((lane >> 4) & 1) * 8;
    const int b_colb = ((lane >> 3) & 1) * 16;

    for (int kt = 0; kt < KT; kt++) {
        // Tail-correct drain: group kt must be complete before reading stage kt%4.
        if (kt <= KT - 3)      CP_WAIT(2);
        else if (kt == KT - 2) CP_WAIT(1);
        else                   CP_WAIT(0);
        __syncthreads();
        if (kt + 3 < KT) issue(kt + 3);

        char* sA = smem + (kt % NSTG) * STAGE_B;
        char* sB = sA + ATILE_B;
        #pragma unroll
        for (int ks = 0; ks < 2; ks++) {
            uint32_t a[4][4], bfr[2][4];
            #pragma unroll
            for (int mt = 0; mt < 4; mt++) {
                uint32_t addr = smem_u32(sA + (a_row + mt * 16) * STR_B + ks * 32 + a_colb);
                LDSM_X4(a[mt], addr);
            }
            #pragma unroll
            for (int p = 0; p < 2; p++) {
                uint32_t addr = smem_u32(sB + (b_row0 + p * 16) * STR_B + ks * 32 + b_colb);
                LDSM_X4(bfr[p], addr);
            }
            #pragma unroll
            for (int mt = 0; mt < 4; mt++) {
                #pragma unroll
                for (int nt = 0; nt < 4; nt++)
                    mma_f16(acc[mt][nt], a[mt], &bfr[nt >> 1][(nt & 1) * 2]);
            }
        }
    }

    // epilogue: scatter rows to fused positions
    #pragma unroll
    for (int mt = 0; mt < 4; mt++) {
        int gmA = gm0 + wm * 64 + mt * 16 + grp;
        #pragma unroll
        for (int half = 0; half < 2; half++) {
            int gm = gmA + half * 8;
            int bb = gm / nvis;
            int j  = gm - bb * nvis;
            int dst = g_vdst[bb][j];
            if (dst < 0) continue;
            float* orow = out_fused + ((size_t)bb * L + dst) * DMODEL + nb0;
            #pragma unroll
            for (int nt = 0; nt < 4; nt++) {
                int col = wn * 32 + nt * 8 + qid * 2;
                float2 v;
                v.x = acc[mt][nt][half * 2 + 0] + sBias[col];
                v.y = acc[mt][nt][half * 2 + 1] + sBias[col + 1];
                __stcs(reinterpret_cast<float2*>(orow + col), v);
            }
        }
    }

    // drain background mask writes before CTA exit
    if (hasMask) BULK_WAIT0();
}

// ---------------- host launch ----------------
extern "C" void kernel_launch(void* const* d_in, const int* in_sizes, int n_in,
                              void* d_out, int out_size) {
    const float* visual = (const float*)d_in[0];
    const float* emb    = (const float*)d_in[1];
    const float* Wp     = (const float*)d_in[2];
    const float* bp     = (const float*)d_in[3];
    const int*   texts  = (const int*)d_in[4];
    const int*   img_id = (const int*)d_in[5];

    const int D    = in_sizes[3];               // 1024
    const int DV   = in_sizes[2] / D;           // 1152
    const int nvis = in_sizes[0] / (NB * DV);   // 2304
    (void)n_in;

    double osB = (double)out_size / (double)NB;
    int L = (int)((-(double)DMODEL + sqrt((double)DMODEL * DMODEL + 4.0 * osB)) / 2.0 + 0.5);

    float* out_fused = (float*)d_out;
    float* out_mask  = (float*)d_out + (size_t)NB * L * DMODEL;
    const int Mtot = NB * nvis;  // 18432

    const int nGemm    = (DMODEL / GBN) * (Mtot / GBM);  // 1152
    const int mRowBlks = (L + 31) / 32;                  // 136
    const int nMask    = NB * mRowBlks;                  // 1088
    const int nGath    = (NB * L + 31) / 32;             // 1087

    const int n8    = Mtot * KDIM / 8;
    const int nConv = (n8 + 255) / 256;
    const int nPrep = (KDIM / 32) * (DMODEL / 32);       // 1152

    const int half2 = 2 * ((nGath < nGemm) ? nGath : nGemm);
    const int grid  = half2 + (nGemm - half2 / 2);       // 2239

    cudaFuncSetAttribute(fused_kernel, cudaFuncAttributeMaxDynamicSharedMemorySize, GEMM_SMEM);

    prologue_kernel<<<nConv + nPrep + NB, 256>>>(visual, Wp, texts, img_id,
                                                 nvis, L, n8, nConv, nPrep);

    fused_kernel<<<grid, 256, GEMM_SMEM>>>(bp, emb, texts, out_fused, out_mask,
                                           nvis, L, nGemm, nMask, nGath, mRowBlks);
}

// round 14
// speedup vs baseline: 1.0412x; 1.0412x over previous
#include <cuda_runtime.h>
#include <cuda_fp16.h>
#include <cstdint>
#include <math.h>

#define NB 8
#define SLEN 2048
#define DMODEL 1024
#define KDIM 1152
#define LMAX 4608
#define NVMAX 4608
#define MTOT (NB * 2304)   // 18432

// ---------------- device-global scratch (no allocs allowed) ----------------
__device__ int g_src[NB][LMAX];    // >=0: gather text pos; -2: visual (GEMM writes); -1: pad
__device__ int g_X[NB][LMAX];      // mask row r: ones for c < X_r, zeros after
__device__ int g_vdst[NB][NVMAX];  // visual token j -> fused row (or -1)
__device__ __half g_Ah[(size_t)MTOT * KDIM];     // visual features as fp16 (42.5MB)
__device__ __half g_Wh[(size_t)DMODEL * KDIM];   // W transposed to [N, K] fp16 (2.4MB)

// ---------------- PTX helpers ----------------
__device__ __forceinline__ uint32_t smem_u32(const void* p) {
    uint32_t a;
    asm("{ .reg .u64 t; cvta.to.shared.u64 t, %1; cvt.u32.u64 %0, t; }" : "=r"(a) : "l"(p));
    return a;
}
__device__ __forceinline__ void cp16(void* smem, const void* gmem) {
    uint32_t s = smem_u32(smem);
    asm volatile("cp.async.cg.shared.global [%0], [%1], 16;\n" :: "r"(s), "l"(gmem));
}
#define CP_COMMIT() asm volatile("cp.async.commit_group;\n")
#define CP_WAIT(n)  asm volatile("cp.async.wait_group %0;\n" :: "n"(n))

// TMA bulk store: smem -> global, size multiple of 16, both 16B aligned.
__device__ __forceinline__ void bulk_s2g(void* gptr, const void* sptr, uint32_t bytes) {
    asm volatile("cp.async.bulk.global.shared::cta.bulk_group [%0], [%1], %2;"
                 :: "l"(gptr), "r"(smem_u32(sptr)), "r"(bytes) : "memory");
}
#define BULK_COMMIT() asm volatile("cp.async.bulk.commit_group;" ::: "memory")
#define BULK_WAIT0()  asm volatile("cp.async.bulk.wait_group 0;" ::: "memory")

#define LDSM_X4(r, addr) \
    asm volatile("ldmatrix.sync.aligned.m8n8.x4.shared.b16 {%0,%1,%2,%3}, [%4];" \
        : "=r"((r)[0]), "=r"((r)[1]), "=r"((r)[2]), "=r"((r)[3]) : "r"(addr))

__device__ __forceinline__ void mma_f16(float* d, const uint32_t* a, const uint32_t* b) {
    asm volatile(
        "mma.sync.aligned.m16n8k16.row.col.f32.f16.f16.f32 "
        "{%0,%1,%2,%3}, {%4,%5,%6,%7}, {%8,%9}, {%0,%1,%2,%3};\n"
        : "+f"(d[0]), "+f"(d[1]), "+f"(d[2]), "+f"(d[3])
        : "r"(a[0]), "r"(a[1]), "r"(a[2]), "r"(a[3]), "r"(b[0]), "r"(b[1]));
}

// ============ prologue: plan + conv_a + prep_w in ONE launch ================
__global__ void __launch_bounds__(256) prologue_kernel(
    const float* __restrict__ A,       // visual
    const float* __restrict__ W,
    const int*   __restrict__ texts,
    const int*   __restrict__ img_id_p,
    int nvis, int L, int n8, int nConv, int nPrep)
{
    const int bid = blockIdx.x;
    const int tid = threadIdx.x;

    // ---- type A: conv (fp32 -> fp16 of visual) ----
    if (bid < nConv) {
        int i = bid * 256 + tid;
        if (i >= n8) return;
        const float4* src = reinterpret_cast<const float4*>(A) + (size_t)i * 2;
        float4 v0 = src[0], v1 = src[1];
        float4 o;
        o.x = __uint_as_float((uint32_t)__half_as_ushort(__float2half_rn(v0.x)) |
                              ((uint32_t)__half_as_ushort(__float2half_rn(v0.y)) << 16));
        o.y = __uint_as_float((uint32_t)__half_as_ushort(__float2half_rn(v0.z)) |
                              ((uint32_t)__half_as_ushort(__float2half_rn(v0.w)) << 16));
        o.z = __uint_as_float((uint32_t)__half_as_ushort(__float2half_rn(v1.x)) |
                              ((uint32_t)__half_as_ushort(__float2half_rn(v1.y)) << 16));
        o.w = __uint_as_float((uint32_t)__half_as_ushort(__float2half_rn(v1.z)) |
                              ((uint32_t)__half_as_ushort(__float2half_rn(v1.w)) << 16));
        __stcs(reinterpret_cast<float4*>(g_Ah) + i, o);
        return;
    }

    __shared__ float t[32][33];       // prep
    __shared__ int s_pos[64];         // plan
    __shared__ int s_n;

    // ---- type B: prep_w (transpose W -> [N,K] fp16) ----
    if (bid < nConv + nPrep) {
        int sub = bid - nConv;
        int k0 = (sub % (KDIM / 32)) * 32;
        int n0 = (sub / (KDIM / 32)) * 32;
        int tx = tid & 31, ty = tid >> 5;
        #pragma unroll
        for (int i = ty; i < 32; i += 8)
            t[i][tx] = W[(size_t)(k0 + i) * DMODEL + n0 + tx];
        __syncthreads();
        #pragma unroll
        for (int i = ty; i < 32; i += 8)
            g_Wh[(size_t)(n0 + i) * KDIM + k0 + tx] = __float2half_rn(t[tx][i]);
        return;
    }

    // ---- type C: plan ----
    int b = bid - nConv - nPrep;
    int img_id = *img_id_p;
    const int* tx_ = texts + b * SLEN;
    if (tid == 0) s_n = 0;
    __syncthreads();
    for (int p = tid; p < SLEN; p += blockDim.x)
        if (tx_[p] == img_id) { int k = atomicAdd(&s_n, 1); if (k < 64) s_pos[k] = p; }
    __syncthreads();
    int n = min(s_n, 64);
    if (tid == 0) {
        for (int i = 1; i < n; i++) {
            int v = s_pos[i]; int j = i - 1;
            while (j >= 0 && s_pos[j] > v) { s_pos[j + 1] = s_pos[j]; j--; }
            s_pos[j + 1] = v;
        }
    }
    __syncthreads();
    int per = (n > 0) ? (nvis / n) : 0;
    int len = (n > 0) ? (SLEN - n + n * per) : SLEN;
    for (int p = tid; p < SLEN; p += blockDim.x) {
        if (tx_[p] == img_id) continue;
        int k = 0;
        while (k < n && s_pos[k] < p) k++;
        int fp = (p - k) + k * per;
        g_src[b][fp] = p;
        g_X[b][fp]   = fp + 1;
    }
    for (int j = tid; j < nvis; j += blockDim.x) {
        int dst = -1;
        if (n > 0 && j < n * per) {
            int i = j / per;
            dst = (s_pos[i] - i) + i * per + (j - i * per);
            g_src[b][dst] = -2;
            g_X[b][dst]   = (s_pos[i] - i) + (i + 1) * per;
        }
        g_vdst[b][j] = dst;
    }
    for (int l = len + tid; l < L; l += blockDim.x) { g_src[b][l] = -1; g_X[b][l] = 0; }
}

// ==== fused kernel: even=gemm, odd=mover (mask on TMA engine + gather) =====
#define GBM 128
#define GBN 128
#define GBK 32
#define STR_B 80                     // bytes per smem row (40 halves, ldmatrix conflict-free)
#define ATILE_B (128 * STR_B)        // 10240
#define STAGE_B (2 * ATILE_B)        // 20480
#define NSTG 4
#define GEMM_SMEM (NSTG * STAGE_B + 1024)   // 82944; 2 CTAs/SM

__global__ void __launch_bounds__(256, 2) fused_kernel(
    const float* __restrict__ bias,
    const float* __restrict__ emb,
    const int*   __restrict__ texts,
    float* __restrict__ out_fused,
    float* __restrict__ out_mask,
    int nvis, int L, int nGemm, int nMask, int nGath, int mRowBlks)
{
    extern __shared__ char smem[];
    const int bid = blockIdx.x;
    const int sub = bid >> 1;
    const int tid = threadIdx.x;
    const int wid = tid >> 5, lane = tid & 31;

    // ---------- odd blocks: mover = mask (TMA bulk) + gather ----------
    if (bid & 1) {
        __shared__ int sX[32];
        const bool hasMask = (sub < nMask);
        int mb = 0, mr0 = 0, mrmax = 0;
        if (hasMask) {
            // smem: ones[L] at 0, zeros[L] at 4*LMAX (16B aligned; fits in 82944)
            float* ones  = reinterpret_cast<float*>(smem);
            float* zeros = reinterpret_cast<float*>(smem + 4 * LMAX);
            for (int i = tid; i < L; i += 256) { ones[i] = 1.f; zeros[i] = 0.f; }
            mb    = sub / mRowBlks;
            mr0   = (sub - mb * mRowBlks) * 32;
            mrmax = min(32, L - mr0);
            if (tid < 32) sX[tid] = (mr0 + tid < L) ? g_X[mb][mr0 + tid] : 0;
            __syncthreads();
            asm volatile("fence.proxy.async.shared::cta;" ::: "memory");
            if (tid < mrmax) {
                int X = sX[tid];
                if (X < 0) X = 0;
                if (X > L) X = L;
                float* grow = out_mask + ((size_t)mb * L + mr0 + tid) * (size_t)L;
                int bytes1 = X * 4;
                int n1  = bytes1 & ~15;            // ones bulk prefix
                int c16 = (bytes1 + 15) & ~15;     // zeros bulk start
                if (n1 > 0) bulk_s2g(grow, ones, (uint32_t)n1);
                if (c16 > n1) {                    // boundary 16B: scalar stores
                    #pragma unroll
                    for (int f = 0; f < 4; f++) {
                        int idx = (n1 >> 2) + f;
                        grow[idx] = (idx < X) ? 1.f : 0.f;
                    }
                }
                int zbytes = L * 4 - c16;
                if (zbytes > 0) bulk_s2g((char*)grow + c16, zeros, (uint32_t)zbytes);
            }
            BULK_COMMIT();
        }

        // gather runs while the TMA bulk stores drain in the background
        if (sub < nGath) {
            #pragma unroll
            for (int i = 0; i < 4; i++) {
                int row = sub * 32 + wid * 4 + i;
                if (row >= NB * L) break;
                int b = row / L, l = row - b * L;
                int src = g_src[b][l];
                if (src == -2) continue;  // visual row: GEMM epilogue writes it
                float4* dst = reinterpret_cast<float4*>(out_fused + ((size_t)b * L + l) * DMODEL);
                if (src < 0) {
                    float4 z = make_float4(0.f, 0.f, 0.f, 0.f);
                    #pragma unroll
                    for (int k = 0; k < 8; k++) __stcs(dst + lane + k * 32, z);
                    continue;
                }
                int tok = texts[b * SLEN + src];
                const float4* s = reinterpret_cast<const float4*>(emb + (size_t)tok * DMODEL);
                float4 v[8];
                #pragma unroll
                for (int k = 0; k < 8; k++) v[k] = s[lane + k * 32];
                #pragma unroll
                for (int k = 0; k < 8; k++) __stcs(dst + lane + k * 32, v[k]);
            }
        }

        if (hasMask) BULK_WAIT0();   // drain background mask writes before exit
        return;
    }

    // ------------------------- even blocks: gemm ---------------------------
    if (sub >= nGemm) return;
    float* sBias = reinterpret_cast<float*>(smem + NSTG * STAGE_B);

    const int nb0 = (sub & 7) * GBN;        // 8 N-blocks (DMODEL/128)
    const int gm0 = (sub >> 3) * GBM;
    const int wm = wid & 1;       // 2 warps along M (64 rows)
    const int wn = wid >> 1;      // 4 warps along N (32 cols)
    const int grp = lane >> 2;
    const int qid = lane & 3;

    if (tid < 128) sBias[tid] = bias[nb0 + tid];

    const __half* Ag = g_Ah + (size_t)gm0 * KDIM;
    const __half* Bg = g_Wh + (size_t)nb0 * KDIM;

    float acc[4][4][4];
    #pragma unroll
    for (int i = 0; i < 4; i++)
        #pragma unroll
        for (int j = 0; j < 4; j++)
            #pragma unroll
            for (int k = 0; k < 4; k++) acc[i][j][k] = 0.f;

    const int KT = KDIM / GBK;  // 36

    auto issue = [&](int kt) {
        int s = kt % NSTG;
        char* dA = smem + s * STAGE_B;
        char* dB = dA + ATILE_B;
        #pragma unroll
        for (int v = tid; v < 512; v += 256) {
            int row = v >> 2, c = v & 3;
            cp16(dA + row * STR_B + c * 16, Ag + (size_t)row * KDIM + kt * GBK + c * 8);
        }
        #pragma unroll
        for (int v = tid; v < 512; v += 256) {
            int row = v >> 2, c = v & 3;
            cp16(dB + row * STR_B + c * 16, Bg + (size_t)row * KDIM + kt * GBK + c * 8);
        }
        CP_COMMIT();
    };

    issue(0);
    issue(1);
    issue(2);

    const int a_row = wm * 64 + (lane & 15);
    const int a_colb = (lane >> 4) * 16;
    const int b_row0 = wn * 32 + (lane & 7) + ((lane >> 4) & 1) * 8;
    const int b_colb = ((lane >> 3) & 1) * 16;

    for (int kt = 0; kt < KT; kt++) {
        // Tail-correct drain: group kt must be complete before reading stage kt%4.
        if (kt <= KT - 3)      CP_WAIT(2);
        else if (kt == KT - 2) CP_WAIT(1);
        else                   CP_WAIT(0);
        __syncthreads();
        if (kt + 3 < KT) issue(kt + 3);

        char* sA = smem + (kt % NSTG) * STAGE_B;
        char* sB = sA + ATILE_B;
        #pragma unroll
        for (int ks = 0; ks < 2; ks++) {
            uint32_t a[4][4], bfr[2][4];
            #pragma unroll
            for (int mt = 0; mt < 4; mt++) {
                uint32_t addr = smem_u32(sA + (a_row + mt * 16) * STR_B + ks * 32 + a_colb);
                LDSM_X4(a[mt], addr);
            }
            #pragma unroll
            for (int p = 0; p < 2; p++) {
                uint32_t addr = smem_u32(sB + (b_row0 + p * 16) * STR_B + ks * 32 + b_colb);
                LDSM_X4(bfr[p], addr);
            }
            #pragma unroll
            for (int mt = 0; mt < 4; mt++) {
                #pragma unroll
                for (int nt = 0; nt < 4; nt++)
                    mma_f16(acc[mt][nt], a[mt], &bfr[nt >> 1][(nt & 1) * 2]);
            }
        }
    }

    // epilogue: scatter rows to fused positions
    #pragma unroll
    for (int mt = 0; mt < 4; mt++) {
        int gmA = gm0 + wm * 64 + mt * 16 + grp;
        #pragma unroll
        for (int half = 0; half < 2; half++) {
            int gm = gmA + half * 8;
            int bb = gm / nvis;
            int j  = gm - bb * nvis;
            int dst = g_vdst[bb][j];
            if (dst < 0) continue;
            float* orow = out_fused + ((size_t)bb * L + dst) * DMODEL + nb0;
            #pragma unroll
            for (int nt = 0; nt < 4; nt++) {
                int col = wn * 32 + nt * 8 + qid * 2;
                float2 v;
                v.x = acc[mt][nt][half * 2 + 0] + sBias[col];
                v.y = acc[mt][nt][half * 2 + 1] + sBias[col + 1];
                __stcs(reinterpret_cast<float2*>(orow + col), v);
            }
        }
    }
}

// ---------------- host launch ----------------
extern "C" void kernel_launch(void* const* d_in, const int* in_sizes, int n_in,
                              void* d_out, int out_size) {
    const float* visual = (const float*)d_in[0];
    const float* emb    = (const float*)d_in[1];
    const float* Wp     = (const float*)d_in[2];
    const float* bp     = (const float*)d_in[3];
    const int*   texts  = (const int*)d_in[4];
    const int*   img_id = (const int*)d_in[5];

    const int D    = in_sizes[3];               // 1024
    const int DV   = in_sizes[2] / D;           // 1152
    const int nvis = in_sizes[0] / (NB * DV);   // 2304
    (void)n_in;

    double osB = (double)out_size / (double)NB;
    int L = (int)((-(double)DMODEL + sqrt((double)DMODEL * DMODEL + 4.0 * osB)) / 2.0 + 0.5);

    float* out_fused = (float*)d_out;
    float* out_mask  = (float*)d_out + (size_t)NB * L * DMODEL;
    const int Mtot = NB * nvis;  // 18432

    const int nGemm    = (DMODEL / GBN) * (Mtot / GBM);  // 1152
    const int mRowBlks = (L + 31) / 32;                  // 136
    const int nMask    = NB * mRowBlks;                  // 1088
    const int nGath    = (NB * L + 31) / 32;             // 1087
    int nMover = (nMask > nGath) ? nMask : nGath;        // 1088
    int gmax2  = (nGemm > nMover) ? nGemm : nMover;      // 1152

    const int n8    = Mtot * KDIM / 8;
    const int nConv = (n8 + 255) / 256;
    const int nPrep = (KDIM / 32) * (DMODEL / 32);       // 1152

    cudaFuncSetAttribute(fused_kernel, cudaFuncAttributeMaxDynamicSharedMemorySize, GEMM_SMEM);

    prologue_kernel<<<nConv + nPrep + NB, 256>>>(visual, Wp, texts, img_id,
                                                 nvis, L, n8, nConv, nPrep);

    fused_kernel<<<2 * gmax2, 256, GEMM_SMEM>>>(bp, emb, texts, out_fused, out_mask,
                                                nvis, L, nGemm, nMask, nGath, mRowBlks);
}

// round 15
// speedup vs baseline: 1.0447x; 1.0034x over previous
#include <cuda_runtime.h>
#include <cuda_fp16.h>
#include <cstdint>
#include <math.h>

#define NB 8
#define SLEN 2048
#define DMODEL 1024
#define KDIM 1152
#define LMAX 4608
#define NVMAX 4608
#define MTOT (NB * 2304)   // 18432

// ---------------- device-global scratch (no allocs allowed) ----------------
__device__ int g_src[NB][LMAX];    // >=0: gather text pos; -2: visual (GEMM writes); -1: pad
__device__ int g_X[NB][LMAX];      // mask row r: ones for c < X_r, zeros after
__device__ int g_vdst[NB][NVMAX];  // visual token j -> fused row (or -1)
__device__ __half g_Ah[(size_t)MTOT * KDIM];     // visual features as fp16 (42.5MB)
__device__ __half g_Wh[(size_t)DMODEL * KDIM];   // W transposed to [N, K] fp16 (2.4MB)

// ---------------- PTX helpers ----------------
__device__ __forceinline__ uint32_t smem_u32(const void* p) {
    uint32_t a;
    asm("{ .reg .u64 t; cvta.to.shared.u64 t, %1; cvt.u32.u64 %0, t; }" : "=r"(a) : "l"(p));
    return a;
}
__device__ __forceinline__ void cp16(void* smem, const void* gmem) {
    uint32_t s = smem_u32(smem);
    asm volatile("cp.async.cg.shared.global [%0], [%1], 16;\n" :: "r"(s), "l"(gmem));
}
#define CP_COMMIT() asm volatile("cp.async.commit_group;\n")
#define CP_WAIT(n)  asm volatile("cp.async.wait_group %0;\n" :: "n"(n))

// TMA bulk store: smem -> global, size multiple of 16, both 16B aligned.
// bulk-group counters are separate from cp.async.cg groups.
__device__ __forceinline__ void bulk_s2g(void* gptr, const void* sptr, uint32_t bytes) {
    asm volatile("cp.async.bulk.global.shared::cta.bulk_group [%0], [%1], %2;"
                 :: "l"(gptr), "r"(smem_u32(sptr)), "r"(bytes) : "memory");
}
#define BULK_COMMIT()    asm volatile("cp.async.bulk.commit_group;" ::: "memory")
#define BULK_WAIT_READ() asm volatile("cp.async.bulk.wait_group.read 0;" ::: "memory")

#define LDSM_X4(r, addr) \
    asm volatile("ldmatrix.sync.aligned.m8n8.x4.shared.b16 {%0,%1,%2,%3}, [%4];" \
        : "=r"((r)[0]), "=r"((r)[1]), "=r"((r)[2]), "=r"((r)[3]) : "r"(addr))

__device__ __forceinline__ void mma_f16(float* d, const uint32_t* a, const uint32_t* b) {
    asm volatile(
        "mma.sync.aligned.m16n8k16.row.col.f32.f16.f16.f32 "
        "{%0,%1,%2,%3}, {%4,%5,%6,%7}, {%8,%9}, {%0,%1,%2,%3};\n"
        : "+f"(d[0]), "+f"(d[1]), "+f"(d[2]), "+f"(d[3])
        : "r"(a[0]), "r"(a[1]), "r"(a[2]), "r"(a[3]), "r"(b[0]), "r"(b[1]));
}

// ============ prologue: plan + conv_a + prep_w in ONE launch ================
__global__ void __launch_bounds__(256) prologue_kernel(
    const float* __restrict__ A,       // visual
    const float* __restrict__ W,
    const int*   __restrict__ texts,
    const int*   __restrict__ img_id_p,
    int nvis, int L, int n8, int nConv, int nPrep)
{
    const int bid = blockIdx.x;
    const int tid = threadIdx.x;

    // ---- type A: conv (fp32 -> fp16 of visual) ----
    if (bid < nConv) {
        int i = bid * 256 + tid;
        if (i >= n8) return;
        const float4* src = reinterpret_cast<const float4*>(A) + (size_t)i * 2;
        float4 v0 = src[0], v1 = src[1];
        float4 o;
        o.x = __uint_as_float((uint32_t)__half_as_ushort(__float2half_rn(v0.x)) |
                              ((uint32_t)__half_as_ushort(__float2half_rn(v0.y)) << 16));
        o.y = __uint_as_float((uint32_t)__half_as_ushort(__float2half_rn(v0.z)) |
                              ((uint32_t)__half_as_ushort(__float2half_rn(v0.w)) << 16));
        o.z = __uint_as_float((uint32_t)__half_as_ushort(__float2half_rn(v1.x)) |
                              ((uint32_t)__half_as_ushort(__float2half_rn(v1.y)) << 16));
        o.w = __uint_as_float((uint32_t)__half_as_ushort(__float2half_rn(v1.z)) |
                              ((uint32_t)__half_as_ushort(__float2half_rn(v1.w)) << 16));
        __stcs(reinterpret_cast<float4*>(g_Ah) + i, o);
        return;
    }

    __shared__ float t[32][33];       // prep
    __shared__ int s_pos[64];         // plan
    __shared__ int s_n;

    // ---- type B: prep_w (transpose W -> [N,K] fp16) ----
    if (bid < nConv + nPrep) {
        int sub = bid - nConv;
        int k0 = (sub % (KDIM / 32)) * 32;
        int n0 = (sub / (KDIM / 32)) * 32;
        int tx = tid & 31, ty = tid >> 5;
        #pragma unroll
        for (int i = ty; i < 32; i += 8)
            t[i][tx] = W[(size_t)(k0 + i) * DMODEL + n0 + tx];
        __syncthreads();
        #pragma unroll
        for (int i = ty; i < 32; i += 8)
            g_Wh[(size_t)(n0 + i) * KDIM + k0 + tx] = __float2half_rn(t[tx][i]);
        return;
    }

    // ---- type C: plan ----
    int b = bid - nConv - nPrep;
    int img_id = *img_id_p;
    const int* tx_ = texts + b * SLEN;
    if (tid == 0) s_n = 0;
    __syncthreads();
    for (int p = tid; p < SLEN; p += blockDim.x)
        if (tx_[p] == img_id) { int k = atomicAdd(&s_n, 1); if (k < 64) s_pos[k] = p; }
    __syncthreads();
    int n = min(s_n, 64);
    if (tid == 0) {
        for (int i = 1; i < n; i++) {
            int v = s_pos[i]; int j = i - 1;
            while (j >= 0 && s_pos[j] > v) { s_pos[j + 1] = s_pos[j]; j--; }
            s_pos[j + 1] = v;
        }
    }
    __syncthreads();
    int per = (n > 0) ? (nvis / n) : 0;
    int len = (n > 0) ? (SLEN - n + n * per) : SLEN;
    for (int p = tid; p < SLEN; p += blockDim.x) {
        if (tx_[p] == img_id) continue;
        int k = 0;
        while (k < n && s_pos[k] < p) k++;
        int fp = (p - k) + k * per;
        g_src[b][fp] = p;
        g_X[b][fp]   = fp + 1;
    }
    for (int j = tid; j < nvis; j += blockDim.x) {
        int dst = -1;
        if (n > 0 && j < n * per) {
            int i = j / per;
            dst = (s_pos[i] - i) + i * per + (j - i * per);
            g_src[b][dst] = -2;
            g_X[b][dst]   = (s_pos[i] - i) + (i + 1) * per;
        }
        g_vdst[b][j] = dst;
    }
    for (int l = len + tid; l < L; l += blockDim.x) { g_src[b][l] = -1; g_X[b][l] = 0; }
}

// == fused: even=gemm (mask bulk-issued at CTA end, bg drain), odd=gather ===
#define GBM 128
#define GBN 128
#define GBK 32
#define STR_B 80                     // bytes per smem row (40 halves, ldmatrix conflict-free)
#define ATILE_B (128 * STR_B)        // 10240
#define STAGE_B (2 * ATILE_B)        // 20480
#define NSTG 4
#define MCHUNK 4096                  // bulk-store chunk (bytes)
#define OFF_BIAS  (NSTG * STAGE_B)          // 81920
#define OFF_SX    (OFF_BIAS + 512)          // 82432
#define OFF_ONES  (OFF_SX + 128)            // 82560 (16B aligned)
#define OFF_ZEROS (OFF_ONES + MCHUNK)       // 86656
#define GEMM_SMEM (OFF_ZEROS + MCHUNK)      // 90752; 2 CTAs/SM

__global__ void __launch_bounds__(256, 2) fused_kernel(
    const float* __restrict__ bias,
    const float* __restrict__ emb,
    const int*   __restrict__ texts,
    float* __restrict__ out_fused,
    float* __restrict__ out_mask,
    int nvis, int L, int nGemm, int nMask, int nGath, int mRowBlks)
{
    extern __shared__ char smem[];
    const int bid = blockIdx.x;
    const int sub = bid >> 1;
    const int tid = threadIdx.x;
    const int wid = tid >> 5, lane = tid & 31;

    // ------------------- odd blocks: gather only (short) -------------------
    if (bid & 1) {
        if (sub >= nGath) return;
        #pragma unroll
        for (int i = 0; i < 4; i++) {
            int row = sub * 32 + wid * 4 + i;
            if (row >= NB * L) break;
            int b = row / L, l = row - b * L;
            int src = g_src[b][l];
            if (src == -2) continue;  // visual row: GEMM epilogue writes it
            float4* dst = reinterpret_cast<float4*>(out_fused + ((size_t)b * L + l) * DMODEL);
            if (src < 0) {
                float4 z = make_float4(0.f, 0.f, 0.f, 0.f);
                #pragma unroll
                for (int k = 0; k < 8; k++) __stcs(dst + lane + k * 32, z);
                continue;
            }
            int tok = texts[b * SLEN + src];
            const float4* s = reinterpret_cast<const float4*>(emb + (size_t)tok * DMODEL);
            float4 v[8];
            #pragma unroll
            for (int k = 0; k < 8; k++) v[k] = s[lane + k * 32];
            #pragma unroll
            for (int k = 0; k < 8; k++) __stcs(dst + lane + k * 32, v[k]);
        }
        return;
    }

    // -------- even blocks: gemm; mask chunk issued at CTA end-of-life ------
    if (sub >= nGemm) return;
    float* sBias = reinterpret_cast<float*>(smem + OFF_BIAS);
    int*   sXm   = reinterpret_cast<int*>(smem + OFF_SX);
    float* ones  = reinterpret_cast<float*>(smem + OFF_ONES);
    float* zeros = reinterpret_cast<float*>(smem + OFF_ZEROS);

    const int nb0 = (sub & 7) * GBN;        // 8 N-blocks (DMODEL/128)
    const int gm0 = (sub >> 3) * GBM;
    const int wm = wid & 1;       // 2 warps along M (64 rows)
    const int wn = wid >> 1;      // 4 warps along N (32 cols)
    const int grp = lane >> 2;
    const int qid = lane & 3;

    if (tid < 128) sBias[tid] = bias[nb0 + tid];

    // mask setup (cheap; pattern buffers in dedicated smem, filled once)
    const bool hasMask = (sub < nMask);
    int mb = 0, mr0 = 0, mrmax = 0;
    if (hasMask) {
        mb    = sub / mRowBlks;
        mr0   = (sub - mb * mRowBlks) * 32;
        mrmax = min(32, L - mr0);
        for (int i = tid; i < MCHUNK / 4; i += 256) { ones[i] = 1.f; zeros[i] = 0.f; }
        if (tid < 32) sXm[tid] = (mr0 + tid < L) ? g_X[mb][mr0 + tid] : 0;
    }

    const __half* Ag = g_Ah + (size_t)gm0 * KDIM;
    const __half* Bg = g_Wh + (size_t)nb0 * KDIM;

    float acc[4][4][4];
    #pragma unroll
    for (int i = 0; i < 4; i++)
        #pragma unroll
        for (int j = 0; j < 4; j++)
            #pragma unroll
            for (int k = 0; k < 4; k++) acc[i][j][k] = 0.f;

    const int KT = KDIM / GBK;  // 36

    auto issue = [&](int kt) {
        int s = kt % NSTG;
        char* dA = smem + s * STAGE_B;
        char* dB = dA + ATILE_B;
        #pragma unroll
        for (int v = tid; v < 512; v += 256) {
            int row = v >> 2, c = v & 3;
            cp16(dA + row * STR_B + c * 16, Ag + (size_t)row * KDIM + kt * GBK + c * 8);
        }
        #pragma unroll
        for (int v = tid; v < 512; v += 256) {
            int row = v >> 2, c = v & 3;
            cp16(dB + row * STR_B + c * 16, Bg + (size_t)row * KDIM + kt * GBK + c * 8);
        }
        CP_COMMIT();
    };

    issue(0);
    issue(1);
    issue(2);

    const int a_row = wm * 64 + (lane & 15);
    const int a_colb = (lane >> 4) * 16;
    const int b_row0 = wn * 32 + (lane & 7) + ((lane >> 4) & 1) * 8;
    const int b_colb = ((lane >> 3) & 1) * 16;

    for (int kt = 0; kt < KT; kt++) {
        // Tail-correct drain: group kt must be complete before reading stage kt%4.
        if (kt <= KT - 3)      CP_WAIT(2);
        else if (kt == KT - 2) CP_WAIT(1);
        else                   CP_WAIT(0);
        __syncthreads();
        if (kt + 3 < KT) issue(kt + 3);

        char* sA = smem + (kt % NSTG) * STAGE_B;
        char* sB = sA + ATILE_B;
        #pragma unroll
        for (int ks = 0; ks < 2; ks++) {
            uint32_t a[4][4], bfr[2][4];
            #pragma unroll
            for (int mt = 0; mt < 4; mt++) {
                uint32_t addr = smem_u32(sA + (a_row + mt * 16) * STR_B + ks * 32 + a_colb);
                LDSM_X4(a[mt], addr);
            }
            #pragma unroll
            for (int p = 0; p < 2; p++) {
                uint32_t addr = smem_u32(sB + (b_row0 + p * 16) * STR_B + ks * 32 + b_colb);
                LDSM_X4(bfr[p], addr);
            }
            #pragma unroll
            for (int mt = 0; mt < 4; mt++) {
                #pragma unroll
                for (int nt = 0; nt < 4; nt++)
                    mma_f16(acc[mt][nt], a[mt], &bfr[nt >> 1][(nt & 1) * 2]);
            }
        }
    }

    // ---- mask: issue bulk stores now; drain continues after CTA exits ----
    // (pattern writes ordered by the k-loop's barriers; make them visible
    //  to the async proxy, then 32 threads post ~10 bulk ops each)
    if (hasMask) {
        asm volatile("fence.proxy.async.shared::cta;" ::: "memory");
        if (tid < mrmax) {
            int X = sXm[tid];
            if (X < 0) X = 0;
            if (X > L) X = L;
            float* grow = out_mask + ((size_t)mb * L + mr0 + tid) * (size_t)L;
            int bytes1 = X * 4;
            int n1  = bytes1 & ~15;            // ones bulk prefix (16B mult)
            int c16 = (bytes1 + 15) & ~15;     // zeros bulk start
            for (int off = 0; off < n1; off += MCHUNK) {
                int len = n1 - off; if (len > MCHUNK) len = MCHUNK;
                bulk_s2g((char*)grow + off, ones, (uint32_t)len);
            }
            if (c16 > n1) {                    // boundary 16B via scalar STG
                #pragma unroll
                for (int f = 0; f < 4; f++) {
                    int idx = (n1 >> 2) + f;
                    grow[idx] = (idx < X) ? 1.f : 0.f;
                }
            }
            int zb = L * 4 - c16;
            for (int off = 0; off < zb; off += MCHUNK) {
                int len = zb - off; if (len > MCHUNK) len = MCHUNK;
                bulk_s2g((char*)grow + c16 + off, zeros, (uint32_t)len);
            }
        }
        BULK_COMMIT();
    }

    // epilogue: scatter rows to fused positions (overlaps TMA smem reads)
    #pragma unroll
    for (int mt = 0; mt < 4; mt++) {
        int gmA = gm0 + wm * 64 + mt * 16 + grp;
        #pragma unroll
        for (int half = 0; half < 2; half++) {
            int gm = gmA + half * 8;
            int bb = gm / nvis;
            int j  = gm - bb * nvis;
            int dst = g_vdst[bb][j];
            if (dst < 0) continue;
            float* orow = out_fused + ((size_t)bb * L + dst) * DMODEL + nb0;
            #pragma unroll
            for (int nt = 0; nt < 4; nt++) {
                int col = wn * 32 + nt * 8 + qid * 2;
                float2 v;
                v.x = acc[mt][nt][half * 2 + 0] + sBias[col];
                v.y = acc[mt][nt][half * 2 + 1] + sBias[col + 1];
                __stcs(reinterpret_cast<float2*>(orow + col), v);
            }
        }
    }

    // wait only until the TMA engine has READ our smem (not full drain):
    // smem can then be safely reassigned to the next CTA while writes land.
    if (hasMask) BULK_WAIT_READ();
}

// ---------------- host launch ----------------
extern "C" void kernel_launch(void* const* d_in, const int* in_sizes, int n_in,
                              void* d_out, int out_size) {
    const float* visual = (const float*)d_in[0];
    const float* emb    = (const float*)d_in[1];
    const float* Wp     = (const float*)d_in[2];
    const float* bp     = (const float*)d_in[3];
    const int*   texts  = (const int*)d_in[4];
    const int*   img_id = (const int*)d_in[5];

    const int D    = in_sizes[3];               // 1024
    const int DV   = in_sizes[2] / D;           // 1152
    const int nvis = in_sizes[0] / (NB * DV);   // 2304
    (void)n_in;

    double osB = (double)out_size / (double)NB;
    int L = (int)((-(double)DMODEL + sqrt((double)DMODEL * DMODEL + 4.0 * osB)) / 2.0 + 0.5);

    float* out_fused = (float*)d_out;
    float* out_mask  = (float*)d_out + (size_t)NB * L * DMODEL;
    const int Mtot = NB * nvis;  // 18432

    const int nGemm    = (DMODEL / GBN) * (Mtot / GBM);  // 1152
    const int mRowBlks = (L + 31) / 32;                  // 136
    const int nMask    = NB * mRowBlks;                  // 1088
    const int nGath    = (NB * L + 31) / 32;             // 1087
    int gmax2 = (nGemm > nGath) ? nGemm : nGath;         // 1152

    const int n8    = Mtot * KDIM / 8;
    const int nConv = (n8 + 255) / 256;
    const int nPrep = (KDIM / 32) * (DMODEL / 32);       // 1152

    cudaFuncSetAttribute(fused_kernel, cudaFuncAttributeMaxDynamicSharedMemorySize, GEMM_SMEM);

    prologue_kernel<<<nConv + nPrep + NB, 256>>>(visual, Wp, texts, img_id,
                                                 nvis, L, n8, nConv, nPrep);

    fused_kernel<<<2 * gmax2, 256, GEMM_SMEM>>>(bp, emb, texts, out_fused, out_mask,
                                                nvis, L, nGemm, nMask, nGath, mRowBlks);
}